// round 8
// baseline (speedup 1.0000x reference)
#include <cuda_runtime.h>

// DIN HistAttentionSeqPoolingLayer — SMEM-staged, folded layer-1,
// h-register-blocked (x8) MLP to kill the SMEM-crossbar bottleneck.
// B=4096, T=200, E=64, H1=80, H2=40.
// out[b][e] = sum_{t<len_b} score(b,t) * keys[b][t][e]
// Fold: pre1_h = c_h + sum_e k_e * V[h][e]
//   c_h = b1_h + sum_e q_e*(W1a+W1c)_{eh}
//   V[h][e] = (W1b - W1c)_{eh} + q_e * W1d_{eh}

#define BB 4096
#define TT 200
#define EE 64
#define HH1 80
#define HH2 40
#define NTHREADS 224
#define HBLK 8             // h-register-block: K element reused 8x per LDS
#define KPAD 68            // K row stride: 68 mod 32 = 4 -> conflict-free LDS.128

// smem layout (floats)
#define OFF_K    0                       // 200*68 = 13600
#define OFF_V    (OFF_K + TT*KPAD)       // 80*64  = 5120
#define OFF_W2   (OFF_V + HH1*EE)        // 80*40  = 3200
#define OFF_Q    (OFF_W2 + HH1*HH2)      // 64
#define OFF_C    (OFF_Q + EE)            // 80
#define OFF_WD   (OFF_C + HH1)           // 40
#define OFF_B2   (OFF_WD + HH2)          // 40
#define OFF_SC   (OFF_B2 + HH2)          // 200
#define OFF_PART (OFF_SC + TT)           // 192
#define SMEM_FLOATS (OFF_PART + 3*EE)
#define SMEM_BYTES  (SMEM_FLOATS * 4)

__global__ __launch_bounds__(NTHREADS, 2)
void din_pool_kernel(const float* __restrict__ query,
                     const float* __restrict__ keys,
                     const int*   __restrict__ keys_length,
                     const float* __restrict__ W1,
                     const float* __restrict__ b1,
                     const float* __restrict__ W2,
                     const float* __restrict__ b2,
                     const float* __restrict__ Wd,
                     const float* __restrict__ bd,
                     float* __restrict__ out)
{
    extern __shared__ float sm[];
    float* Ksm  = sm + OFF_K;
    float* Vsm  = sm + OFF_V;
    float* W2sm = sm + OFF_W2;
    float* qsm  = sm + OFF_Q;
    float* csm  = sm + OFF_C;
    float* Wdsm = sm + OFF_WD;
    float* b2sm = sm + OFF_B2;
    float* scsm = sm + OFF_SC;
    float* part = sm + OFF_PART;

    const int b   = blockIdx.x;
    const int tid = threadIdx.x;
    const int len = keys_length[b];

    // ---- stage q, W2, Wd, b2 + coalesced K staging (rows < len only) ----
    if (tid < EE) qsm[tid] = query[b * EE + tid];
    if (tid < HH2) { Wdsm[tid] = Wd[tid]; b2sm[tid] = b2[tid]; }
    for (int i = tid; i < (HH1 * HH2) / 4; i += NTHREADS)
        reinterpret_cast<float4*>(W2sm)[i] =
            reinterpret_cast<const float4*>(W2)[i];

    {
        const float4* kg = reinterpret_cast<const float4*>(keys + (long)b * TT * EE);
        const int n4 = len * (EE / 4);
        for (int i = tid; i < n4; i += NTHREADS) {
            int t = i >> 4;
            int j = i & 15;
            float4 v = kg[i];
            *reinterpret_cast<float4*>(Ksm + t * KPAD + j * 4) = v;
        }
    }
    __syncthreads();

    // ---- folded per-batch layer-1: V[h][e], c[h] ----
    for (int idx = tid; idx < HH1 * EE; idx += NTHREADS) {
        int h = idx >> 6;
        int e = idx & 63;
        float Bv = W1[(64  + e) * HH1 + h];
        float Cv = W1[(128 + e) * HH1 + h];
        float Dv = W1[(192 + e) * HH1 + h];
        Vsm[h * EE + e] = Bv - Cv + qsm[e] * Dv;
    }
    for (int h = tid; h < HH1; h += NTHREADS) {
        float s = b1[h];
        #pragma unroll 8
        for (int e = 0; e < EE; e++)
            s += qsm[e] * (W1[e * HH1 + h] + W1[(128 + e) * HH1 + h]);
        csm[h] = s;
    }
    __syncthreads();

    // ---- per-thread-t MLP, h blocked by 8 (K LDS amortized 8x) ----
    const int t    = tid;
    const int warp = tid >> 5;
    const bool active = (t < TT) && ((warp << 5) < len);

    float sc = 0.f;
    if (active) {
        const float4* kr = reinterpret_cast<const float4*>(Ksm + t * KPAD);

        float4 a2[HH2 / 4];
        #pragma unroll
        for (int j = 0; j < HH2 / 4; j++)
            a2[j] = reinterpret_cast<const float4*>(b2sm)[j];

        for (int hg = 0; hg < HH1 / HBLK; hg++) {
            const int h0 = hg * HBLK;

            float pre[HBLK];
            #pragma unroll
            for (int hh = 0; hh < HBLK; hh++) pre[hh] = csm[h0 + hh];

            #pragma unroll
            for (int i = 0; i < EE / 4; i++) {
                float4 k4 = kr[i];                  // per-lane, conflict-free
                #pragma unroll
                for (int hh = 0; hh < HBLK; hh++) {
                    float4 v4 = *reinterpret_cast<const float4*>(
                        Vsm + (h0 + hh) * EE + i * 4);   // uniform broadcast
                    pre[hh] = fmaf(k4.x, v4.x, pre[hh]);
                    pre[hh] = fmaf(k4.y, v4.y, pre[hh]);
                    pre[hh] = fmaf(k4.z, v4.z, pre[hh]);
                    pre[hh] = fmaf(k4.w, v4.w, pre[hh]);
                }
            }

            float h1[HBLK];
            #pragma unroll
            for (int hh = 0; hh < HBLK; hh++)
                h1[hh] = 1.f / (1.f + __expf(-pre[hh]));

            #pragma unroll
            for (int j = 0; j < HH2 / 4; j++) {
                float4 acc = a2[j];
                #pragma unroll
                for (int hh = 0; hh < HBLK; hh++) {
                    float4 w = *reinterpret_cast<const float4*>(
                        W2sm + (h0 + hh) * HH2 + j * 4); // uniform broadcast
                    acc.x = fmaf(h1[hh], w.x, acc.x);
                    acc.y = fmaf(h1[hh], w.y, acc.y);
                    acc.z = fmaf(h1[hh], w.z, acc.z);
                    acc.w = fmaf(h1[hh], w.w, acc.w);
                }
                a2[j] = acc;
            }
        }

        sc = bd[0];
        #pragma unroll
        for (int j = 0; j < HH2 / 4; j++) {
            sc += Wdsm[4*j+0] * (1.f / (1.f + __expf(-a2[j].x)));
            sc += Wdsm[4*j+1] * (1.f / (1.f + __expf(-a2[j].y)));
            sc += Wdsm[4*j+2] * (1.f / (1.f + __expf(-a2[j].z)));
            sc += Wdsm[4*j+3] * (1.f / (1.f + __expf(-a2[j].w)));
        }
        if (t >= len) sc = 0.f;          // discard garbage from unstaged rows
    }
    if (t < TT) scsm[t] = sc;
    __syncthreads();

    // ---- pooling: out[e] = sum_{t<len} sc[t] * K[t][e]  (3 t-groups x 64 e) ----
    if (tid < 3 * EE) {
        const int g = tid >> 6;          // uniform per warp (64 | warp boundaries)
        const int e = tid & 63;
        float acc = 0.f;
        for (int tt = g; tt < len; tt += 3)
            acc += scsm[tt] * Ksm[tt * KPAD + e];
        part[tid] = acc;
    }
    __syncthreads();

    if (tid < EE)
        out[b * EE + tid] = part[tid] + part[EE + tid] + part[2 * EE + tid];
}

extern "C" void kernel_launch(void* const* d_in, const int* in_sizes, int n_in,
                              void* d_out, int out_size) {
    const float* query       = (const float*)d_in[0];
    const float* keys        = (const float*)d_in[1];
    const int*   keys_length = (const int*)  d_in[2];
    const float* W1          = (const float*)d_in[3];
    const float* b1          = (const float*)d_in[4];
    const float* W2          = (const float*)d_in[5];
    const float* b2          = (const float*)d_in[6];
    const float* Wd          = (const float*)d_in[7];
    const float* bd          = (const float*)d_in[8];
    float* out = (float*)d_out;

    cudaFuncSetAttribute(din_pool_kernel,
                         cudaFuncAttributeMaxDynamicSharedMemorySize, SMEM_BYTES);

    din_pool_kernel<<<BB, NTHREADS, SMEM_BYTES>>>(query, keys, keys_length,
                                                  W1, b1, W2, b2, Wd, bd, out);
}